// round 14
// baseline (speedup 1.0000x reference)
#include <cuda_runtime.h>
#include <cuda_fp16.h>
#include <cuda_fp8.h>
#include <math.h>

#define N_NODES 20000
#define DIM 128
#define KNB 16
#define STEPS 2
#define LAYERS 2
#define E_EDGES 8192

#define GRID_BLOCKS 592            // 4 * 148 — co-resident with launch_bounds(256,4)
#define TPB 256
#define TOTAL_WARPS (GRID_BLOCKS * (TPB / 32))   // 4736

// Scratch (static __device__ — no allocations allowed; zero-initialized)
__device__ float    g_proj[N_NODES];
__device__ float    g_self[N_NODES];
__device__ float    g_cw[LAYERS * DIM];
__device__ float    g_eloss[E_EDGES];
__device__ volatile int g_bar;     // phase barrier arrive counter (self-resetting)
__device__ int      g_done;        // completion counter (self-resetting)
// fp8 e4m3 copy of embeddings: 128 fp8 per row = 32 uint per row (2.56 MB)
__device__ unsigned g_emb8[N_NODES * 32];

__device__ __forceinline__ float2 fp8x2_to_float2(unsigned short v) {
    __half2_raw hr = __nv_cvt_fp8x2_to_halfraw2((__nv_fp8x2_storage_t)v, __NV_E4M3);
    __half2 h = *reinterpret_cast<__half2*>(&hr);
    return __half22float2(h);
}

// ---------------------------------------------------------------------------
// Single persistent kernel.
// Phase A: block 0 computes cw[l,d] = sum_f layer_w[l,f,d]; all warps
//          stride over nodes computing proj/self + fp8 embedding copy.
// Device barrier (all 592 blocks co-resident).
// Phase C: warps stride over edges; label-1 edges compute both endpoints'
//          attention rows in-register (fp8 gathers), label-0 read fp32 rows;
//          per-edge loss -> g_eloss[e]. Last-done block reduces in fixed
//          order and resets the counters for the next graph replay.
// ---------------------------------------------------------------------------
__global__ void __launch_bounds__(TPB, 4) fused_kernel(
        const float* __restrict__ emb,
        const int*   __restrict__ edges,
        const int*   __restrict__ labels,
        const int*   __restrict__ neighbors,
        const float* __restrict__ fc_w,
        const float* __restrict__ fc_b,
        const float* __restrict__ layer_w,
        const float* __restrict__ layer_b,
        float* __restrict__ out) {
    __shared__ bool is_last;
    const int tid  = threadIdx.x;
    const int lane = tid & 31;
    const int W    = blockIdx.x * (TPB / 32) + (tid >> 5);   // global warp id

    // ---------------- Phase A ----------------
    if (blockIdx.x == 0) {
        int t = tid;                              // 0..255 == LAYERS*DIM
        int l = t >> 7, d = t & 127;
        const float* w = layer_w + l * DIM * DIM + d;
        float s = 0.f;
#pragma unroll 16
        for (int f = 0; f < DIM; f++) s += w[f * DIM];
        g_cw[t] = s;
    }

    {
        float4 wn = reinterpret_cast<const float4*>(fc_w)[lane];
        float4 ws = reinterpret_cast<const float4*>(fc_w + DIM)[lane];
        for (int n = W; n < N_NODES; n += TOTAL_WARPS) {
            float4 e = reinterpret_cast<const float4*>(emb + (size_t)n * DIM)[lane];
            __nv_fp8x4_e4m3 p(e);
            g_emb8[(size_t)n * 32 + lane] = *reinterpret_cast<unsigned*>(&p);
            float pn = e.x*wn.x + e.y*wn.y + e.z*wn.z + e.w*wn.w;
            float ps = e.x*ws.x + e.y*ws.y + e.z*ws.z + e.w*ws.w;
#pragma unroll
            for (int off = 16; off; off >>= 1) {
                pn += __shfl_xor_sync(0xffffffffu, pn, off);
                ps += __shfl_xor_sync(0xffffffffu, ps, off);
            }
            if (lane == 0) { g_proj[n] = pn; g_self[n] = ps; }
        }
    }

    // ---------------- Device barrier ----------------
    __threadfence();
    __syncthreads();
    if (tid == 0) {
        atomicAdd((int*)&g_bar, 1);
        while (g_bar < GRID_BLOCKS) { __nanosleep(64); }
    }
    __syncthreads();
    __threadfence();

    // ---------------- Phase C ----------------
    const float fcb = fc_b[0];
    float4 c0 = reinterpret_cast<const float4*>(g_cw)[lane];
    float4 c1 = reinterpret_cast<const float4*>(g_cw + DIM)[lane];
    float4 b0 = reinterpret_cast<const float4*>(layer_b)[lane];
    float4 b1 = reinterpret_cast<const float4*>(layer_b + DIM)[lane];

    for (int e = W; e < E_EDGES; e += TOTAL_WARPS) {
        int2 ed = *reinterpret_cast<const int2*>(edges + 2 * e);
        int lab = labels[e];

        float4 se, de;
        if (lab == 1) {
            int s = lane >> 4;
            int k = lane & 15;
            int nbA = neighbors[(size_t)s * N_NODES * KNB + (size_t)ed.x * KNB + k];
            int nbB = neighbors[(size_t)s * N_NODES * KNB + (size_t)ed.y * KNB + k];

            // 16-lane-half softmax weights for both endpoints
            float scA = g_proj[nbA] + g_self[ed.x] + fcb;
            float scB = g_proj[nbB] + g_self[ed.y] + fcb;
            scA = (scA >= 0.f) ? scA : 0.2f * scA;
            scB = (scB >= 0.f) ? scB : 0.2f * scB;
            float mA = scA, mB = scB;
#pragma unroll
            for (int off = 8; off; off >>= 1) {
                mA = fmaxf(mA, __shfl_xor_sync(0xffffffffu, mA, off));
                mB = fmaxf(mB, __shfl_xor_sync(0xffffffffu, mB, off));
            }
            float exA = __expf(scA - mA);
            float exB = __expf(scB - mB);
            float suA = exA, suB = exB;
#pragma unroll
            for (int off = 8; off; off >>= 1) {
                suA += __shfl_xor_sync(0xffffffffu, suA, off);
                suB += __shfl_xor_sync(0xffffffffu, suB, off);
            }
            float wgtA = exA / suA;
            float wgtB = exB / suB;

            float4 meA = reinterpret_cast<const float4*>(emb + (size_t)ed.x * DIM)[lane];
            float4 meB = reinterpret_cast<const float4*>(emb + (size_t)ed.y * DIM)[lane];
            float4 aA, aB;
            aA.x = 32.f*meA.x; aA.y = 32.f*meA.y; aA.z = 32.f*meA.z; aA.w = 32.f*meA.w;
            aB.x = 32.f*meB.x; aB.y = 32.f*meB.y; aB.z = 32.f*meB.z; aB.w = 32.f*meB.w;

#pragma unroll
            for (int j = 0; j < 32; j++) {
                float wA = __shfl_sync(0xffffffffu, wgtA, j);
                int   iA = __shfl_sync(0xffffffffu, nbA,  j);
                float wB = __shfl_sync(0xffffffffu, wgtB, j);
                int   iB = __shfl_sync(0xffffffffu, nbB,  j);
                unsigned uA = g_emb8[(size_t)iA * 32 + lane];
                unsigned uB = g_emb8[(size_t)iB * 32 + lane];
                float2 a0 = fp8x2_to_float2((unsigned short)(uA & 0xffffu));
                float2 a1 = fp8x2_to_float2((unsigned short)(uA >> 16));
                float2 q0 = fp8x2_to_float2((unsigned short)(uB & 0xffffu));
                float2 q1 = fp8x2_to_float2((unsigned short)(uB >> 16));
                aA.x += wA * a0.x; aA.y += wA * a0.y;
                aA.z += wA * a1.x; aA.w += wA * a1.y;
                aB.x += wB * q0.x; aB.y += wB * q0.y;
                aB.z += wB * q1.x; aB.w += wB * q1.y;
            }
            se = aA; de = aB;
        } else {
            se = reinterpret_cast<const float4*>(emb + (size_t)ed.x * DIM)[lane];
            de = reinterpret_cast<const float4*>(emb + (size_t)ed.y * DIM)[lane];
        }

        float acc = 0.f;
        {
            float t;
            t = (fmaxf(se.x*c0.x+b0.x,0.f)+fmaxf(se.x*c1.x+b1.x,0.f)) - (fmaxf(de.x*c0.x+b0.x,0.f)+fmaxf(de.x*c1.x+b1.x,0.f)); acc += t*t;
            t = (fmaxf(se.y*c0.y+b0.y,0.f)+fmaxf(se.y*c1.y+b1.y,0.f)) - (fmaxf(de.y*c0.y+b0.y,0.f)+fmaxf(de.y*c1.y+b1.y,0.f)); acc += t*t;
            t = (fmaxf(se.z*c0.z+b0.z,0.f)+fmaxf(se.z*c1.z+b1.z,0.f)) - (fmaxf(de.z*c0.z+b0.z,0.f)+fmaxf(de.z*c1.z+b1.z,0.f)); acc += t*t;
            t = (fmaxf(se.w*c0.w+b0.w,0.f)+fmaxf(se.w*c1.w+b1.w,0.f)) - (fmaxf(de.w*c0.w+b0.w,0.f)+fmaxf(de.w*c1.w+b1.w,0.f)); acc += t*t;
        }
#pragma unroll
        for (int off = 16; off; off >>= 1)
            acc += __shfl_xor_sync(0xffffffffu, acc, off);

        if (lane == 0) {
            float diff = acc * (1.f / (float)DIM);
            float p = expf(-diff);
            float l = (float)lab - p;
            g_eloss[e] = 0.5f * l * l;
        }
    }

    // ---------------- Completion + deterministic reduction ----------------
    __threadfence();
    __syncthreads();
    if (tid == 0) {
        int done = atomicAdd(&g_done, 1);
        is_last = (done == GRID_BLOCKS - 1);
    }
    __syncthreads();

    if (is_last) {
        __shared__ float sh[TPB];
        __threadfence();
        int t = tid;
        float v = 0.f;
#pragma unroll
        for (int i = 0; i < E_EDGES / TPB; i++)
            v += g_eloss[t + i * TPB];
        sh[t] = v;
        __syncthreads();
#pragma unroll
        for (int stride = TPB / 2; stride; stride >>= 1) {
            if (t < stride) sh[t] += sh[t + stride];
            __syncthreads();
        }
        if (t == 0) {
            out[0] = sh[0];
            g_done = 0;        // reset for next graph replay
            g_bar  = 0;
        }
    }
}

// ---------------------------------------------------------------------------
// Inputs (metadata order): 0 edges(i32 E*2), 1 labels(i32 E), 2 neighbors(i32
// STEPS*N*K), 3 embeddings(f32 N*D), 4 fc_w(f32 2D), 5 fc_b(f32 1),
// 6 layer_w(f32 L*D*D), 7 layer_b(f32 L*D). Output: f32 scalar.
// ---------------------------------------------------------------------------
extern "C" void kernel_launch(void* const* d_in, const int* in_sizes, int n_in,
                              void* d_out, int out_size) {
    const int*   edges     = (const int*)  d_in[0];
    const int*   labels    = (const int*)  d_in[1];
    const int*   neighbors = (const int*)  d_in[2];
    const float* emb       = (const float*)d_in[3];
    const float* fc_w      = (const float*)d_in[4];
    const float* fc_b      = (const float*)d_in[5];
    const float* layer_w   = (const float*)d_in[6];
    const float* layer_b   = (const float*)d_in[7];
    float* out = (float*)d_out;

    fused_kernel<<<GRID_BLOCKS, TPB>>>(emb, edges, labels, neighbors,
                                       fc_w, fc_b, layer_w, layer_b, out);
}

// round 15
// speedup vs baseline: 1.4133x; 1.4133x over previous
#include <cuda_runtime.h>
#include <cuda_fp16.h>
#include <cuda_fp8.h>
#include <math.h>

#define N_NODES 20000
#define DIM 128
#define KNB 16
#define STEPS 2
#define LAYERS 2
#define E_EDGES 8192
#define EDGE_WARPS_PER_BLK 8
#define EDGE_BLOCKS (E_EDGES / EDGE_WARPS_PER_BLK)   // 1024

#define PROJ_NODES_PER_WARP 2
#define PROJ_BLOCKS (N_NODES / (PROJ_NODES_PER_WARP * 8))  // 1250

#define FULL 0xffffffffu

// Scratch (static __device__ — no allocations allowed; zero-initialized)
__device__ float    g_proj[N_NODES];
__device__ float    g_self[N_NODES];
__device__ float    g_cw[LAYERS * DIM];
__device__ float    g_partials[EDGE_BLOCKS];
__device__ int      g_edge_count;
// fp8 e4m3 copy of embeddings: 128 fp8 per row = 32 uint per row (2.56 MB)
__device__ unsigned g_emb8[N_NODES * 32];

__device__ __forceinline__ __half2 fp8x2_to_half2(unsigned v) {
    __half2_raw hr = __nv_cvt_fp8x2_to_halfraw2((__nv_fp8x2_storage_t)(unsigned short)v, __NV_E4M3);
    return *reinterpret_cast<__half2*>(&hr);
}

// ---------------------------------------------------------------------------
// K1: fused — proj[n] = emb[n]·w_n, self[n] = emb[n]·w_s, plus fp8 copy of
//     emb. 2 nodes per warp. Block 0 additionally computes
//     cw[l,d] = sum_f layer_w[l,f,d] and resets the edge counter.
// ---------------------------------------------------------------------------
__global__ void __launch_bounds__(256) proj_cw_kernel(
        const float* __restrict__ emb,
        const float* __restrict__ fc_w,
        const float* __restrict__ layer_w) {
    if (blockIdx.x == 0) {
        int t = threadIdx.x;                      // 0..255 == LAYERS*DIM
        int l = t >> 7, d = t & 127;
        const float* w = layer_w + l * DIM * DIM + d;
        float s = 0.f;
#pragma unroll 16
        for (int f = 0; f < DIM; f++) s += w[f * DIM];
        g_cw[t] = s;
        if (t == 0) g_edge_count = 0;
    }

    int warp = (blockIdx.x * blockDim.x + threadIdx.x) >> 5;
    int lane = threadIdx.x & 31;
    int n0 = warp * PROJ_NODES_PER_WARP;
    if (n0 >= N_NODES) return;

    float4 wn = reinterpret_cast<const float4*>(fc_w)[lane];
    float4 ws = reinterpret_cast<const float4*>(fc_w + DIM)[lane];

    float4 e0 = reinterpret_cast<const float4*>(emb + (size_t)(n0 + 0) * DIM)[lane];
    float4 e1 = reinterpret_cast<const float4*>(emb + (size_t)(n0 + 1) * DIM)[lane];

    // fp8 e4m3 copy (coalesced 128B row stores)
    {
        __nv_fp8x4_e4m3 p0(e0);
        __nv_fp8x4_e4m3 p1(e1);
        g_emb8[(size_t)(n0 + 0) * 32 + lane] = *reinterpret_cast<unsigned*>(&p0);
        g_emb8[(size_t)(n0 + 1) * 32 + lane] = *reinterpret_cast<unsigned*>(&p1);
    }

    float pn0 = e0.x*wn.x + e0.y*wn.y + e0.z*wn.z + e0.w*wn.w;
    float ps0 = e0.x*ws.x + e0.y*ws.y + e0.z*ws.z + e0.w*ws.w;
    float pn1 = e1.x*wn.x + e1.y*wn.y + e1.z*wn.z + e1.w*wn.w;
    float ps1 = e1.x*ws.x + e1.y*ws.y + e1.z*ws.z + e1.w*ws.w;

#pragma unroll
    for (int off = 16; off; off >>= 1) {
        pn0 += __shfl_xor_sync(FULL, pn0, off);
        ps0 += __shfl_xor_sync(FULL, ps0, off);
        pn1 += __shfl_xor_sync(FULL, pn1, off);
        ps1 += __shfl_xor_sync(FULL, ps1, off);
    }
    if (lane == 0) {
        g_proj[n0 + 0] = pn0; g_self[n0 + 0] = ps0;
        g_proj[n0 + 1] = pn1; g_self[n0 + 1] = ps1;
    }
}

// ---------------------------------------------------------------------------
// K2: fused edge kernel, one warp per edge.
//     Heavy (label==1): both endpoints' attention rows computed in-register.
//     Gather layout: lane=(r=lane>>4, p=lane&15); lane p loads uint2 (8 fp8)
//     of row 2j+r  ->  2 rows per endpoint per iteration, 16 iterations.
//     half2 accumulation with pre-packed half2 weights.
// ---------------------------------------------------------------------------
__global__ void __launch_bounds__(256) edge_kernel(
        const float* __restrict__ emb,
        const int*   __restrict__ edges,
        const int*   __restrict__ labels,
        const int*   __restrict__ neighbors,
        const float* __restrict__ fc_b,
        const float* __restrict__ layer_b,
        float* __restrict__ out) {
    __shared__ float wsum[EDGE_WARPS_PER_BLK];
    __shared__ bool  is_last;
    int warp_in_blk = threadIdx.x >> 5;
    int lane = threadIdx.x & 31;
    int e = blockIdx.x * EDGE_WARPS_PER_BLK + warp_in_blk;

    int2 ed = *reinterpret_cast<const int2*>(edges + 2 * e);
    int lab = labels[e];

    float4 se, de;
    if (lab == 1) {
        const float fcb = fc_b[0];
        // (step,k) lane view for scores: s = lane>>4, k = lane&15
        int s = lane >> 4;
        int k = lane & 15;
        int nbA = neighbors[(size_t)s * N_NODES * KNB + (size_t)ed.x * KNB + k];
        int nbB = neighbors[(size_t)s * N_NODES * KNB + (size_t)ed.y * KNB + k];

        float scA = g_proj[nbA] + g_self[ed.x] + fcb;
        float scB = g_proj[nbB] + g_self[ed.y] + fcb;
        scA = (scA >= 0.f) ? scA : 0.2f * scA;
        scB = (scB >= 0.f) ? scB : 0.2f * scB;
        float mA = scA, mB = scB;
#pragma unroll
        for (int off = 8; off; off >>= 1) {
            mA = fmaxf(mA, __shfl_xor_sync(FULL, mA, off));
            mB = fmaxf(mB, __shfl_xor_sync(FULL, mB, off));
        }
        float exA = __expf(scA - mA);
        float exB = __expf(scB - mB);
        float suA = exA, suB = exB;
#pragma unroll
        for (int off = 8; off; off >>= 1) {
            suA += __shfl_xor_sync(FULL, suA, off);
            suB += __shfl_xor_sync(FULL, suB, off);
        }
        // pre-packed half2 weights (shuffled as uint in the loop)
        __half2 hwA2 = __float2half2_rn(exA / suA);
        __half2 hwB2 = __float2half2_rn(exB / suB);
        unsigned hwAu = *reinterpret_cast<unsigned*>(&hwA2);
        unsigned hwBu = *reinterpret_cast<unsigned*>(&hwB2);

        // gather layout: r = lane>>4 (row parity), p = lane&15 (8-dim chunk)
        const int r = lane >> 4;
        const int p = lane & 15;

        __half2 aA0 = __float2half2_rn(0.f), aA1 = aA0, aA2 = aA0, aA3 = aA0;
        __half2 aB0 = aA0, aB1 = aA0, aB2 = aA0, aB3 = aA0;

#pragma unroll
        for (int j = 0; j < 16; j++) {
            int idx = 2 * j + r;
            unsigned hwa = __shfl_sync(FULL, hwAu, idx);
            int      ia  = __shfl_sync(FULL, nbA,  idx);
            unsigned hwb = __shfl_sync(FULL, hwBu, idx);
            int      ib  = __shfl_sync(FULL, nbB,  idx);
            uint2 uA = reinterpret_cast<const uint2*>(g_emb8 + (size_t)ia * 32)[p];
            uint2 uB = reinterpret_cast<const uint2*>(g_emb8 + (size_t)ib * 32)[p];
            __half2 hA = *reinterpret_cast<__half2*>(&hwa);
            __half2 hB = *reinterpret_cast<__half2*>(&hwb);
            aA0 = __hfma2(hA, fp8x2_to_half2(uA.x),       aA0);
            aA1 = __hfma2(hA, fp8x2_to_half2(uA.x >> 16), aA1);
            aA2 = __hfma2(hA, fp8x2_to_half2(uA.y),       aA2);
            aA3 = __hfma2(hA, fp8x2_to_half2(uA.y >> 16), aA3);
            aB0 = __hfma2(hB, fp8x2_to_half2(uB.x),       aB0);
            aB1 = __hfma2(hB, fp8x2_to_half2(uB.x >> 16), aB1);
            aB2 = __hfma2(hB, fp8x2_to_half2(uB.y),       aB2);
            aB3 = __hfma2(hB, fp8x2_to_half2(uB.y >> 16), aB3);
        }

        // reduce over the two r-groups (lanes 16 apart hold rows 2j / 2j+1)
        aA0 = __hadd2(aA0, __shfl_xor_sync(FULL, aA0, 16));
        aA1 = __hadd2(aA1, __shfl_xor_sync(FULL, aA1, 16));
        aA2 = __hadd2(aA2, __shfl_xor_sync(FULL, aA2, 16));
        aA3 = __hadd2(aA3, __shfl_xor_sync(FULL, aA3, 16));
        aB0 = __hadd2(aB0, __shfl_xor_sync(FULL, aB0, 16));
        aB1 = __hadd2(aB1, __shfl_xor_sync(FULL, aB1, 16));
        aB2 = __hadd2(aB2, __shfl_xor_sync(FULL, aB2, 16));
        aB3 = __hadd2(aB3, __shfl_xor_sync(FULL, aB3, 16));

        // redistribute: lane l needs dims [4l,4l+4) = regs {2(l&1),2(l&1)+1}
        // of lane p = l>>1 (valid in both halves after the xor-16 add).
        int srcp = lane >> 1;
        __half2 tA0 = __shfl_sync(FULL, aA0, srcp);
        __half2 tA1 = __shfl_sync(FULL, aA1, srcp);
        __half2 tA2 = __shfl_sync(FULL, aA2, srcp);
        __half2 tA3 = __shfl_sync(FULL, aA3, srcp);
        __half2 tB0 = __shfl_sync(FULL, aB0, srcp);
        __half2 tB1 = __shfl_sync(FULL, aB1, srcp);
        __half2 tB2 = __shfl_sync(FULL, aB2, srcp);
        __half2 tB3 = __shfl_sync(FULL, aB3, srcp);
        bool hi = (lane & 1);
        __half2 nA0 = hi ? tA2 : tA0;
        __half2 nA1 = hi ? tA3 : tA1;
        __half2 nB0 = hi ? tB2 : tB0;
        __half2 nB1 = hi ? tB3 : tB1;

        float2 fA0 = __half22float2(nA0);
        float2 fA1 = __half22float2(nA1);
        float2 fB0 = __half22float2(nB0);
        float2 fB1 = __half22float2(nB1);

        // exact fp32 self term: 32 * emb[endpoint]
        float4 meA = reinterpret_cast<const float4*>(emb + (size_t)ed.x * DIM)[lane];
        float4 meB = reinterpret_cast<const float4*>(emb + (size_t)ed.y * DIM)[lane];
        se.x = 32.f*meA.x + fA0.x; se.y = 32.f*meA.y + fA0.y;
        se.z = 32.f*meA.z + fA1.x; se.w = 32.f*meA.w + fA1.y;
        de.x = 32.f*meB.x + fB0.x; de.y = 32.f*meB.y + fB0.y;
        de.z = 32.f*meB.z + fB1.x; de.w = 32.f*meB.w + fB1.y;
    } else {
        se = reinterpret_cast<const float4*>(emb + (size_t)ed.x * DIM)[lane];
        de = reinterpret_cast<const float4*>(emb + (size_t)ed.y * DIM)[lane];
    }

    float4 c0 = reinterpret_cast<const float4*>(g_cw)[lane];
    float4 c1 = reinterpret_cast<const float4*>(g_cw + DIM)[lane];
    float4 b0 = reinterpret_cast<const float4*>(layer_b)[lane];
    float4 b1 = reinterpret_cast<const float4*>(layer_b + DIM)[lane];

    float acc = 0.f;
    {
        float t;
        t = (fmaxf(se.x*c0.x+b0.x,0.f)+fmaxf(se.x*c1.x+b1.x,0.f)) - (fmaxf(de.x*c0.x+b0.x,0.f)+fmaxf(de.x*c1.x+b1.x,0.f)); acc += t*t;
        t = (fmaxf(se.y*c0.y+b0.y,0.f)+fmaxf(se.y*c1.y+b1.y,0.f)) - (fmaxf(de.y*c0.y+b0.y,0.f)+fmaxf(de.y*c1.y+b1.y,0.f)); acc += t*t;
        t = (fmaxf(se.z*c0.z+b0.z,0.f)+fmaxf(se.z*c1.z+b1.z,0.f)) - (fmaxf(de.z*c0.z+b0.z,0.f)+fmaxf(de.z*c1.z+b1.z,0.f)); acc += t*t;
        t = (fmaxf(se.w*c0.w+b0.w,0.f)+fmaxf(se.w*c1.w+b1.w,0.f)) - (fmaxf(de.w*c0.w+b0.w,0.f)+fmaxf(de.w*c1.w+b1.w,0.f)); acc += t*t;
    }
#pragma unroll
    for (int off = 16; off; off >>= 1)
        acc += __shfl_xor_sync(FULL, acc, off);

    if (lane == 0) {
        float diff = acc * (1.f / (float)DIM);
        float p = expf(-diff);
        float l = (float)lab - p;
        wsum[warp_in_blk] = 0.5f * l * l;
    }
    __syncthreads();
    if (threadIdx.x == 0) {
        float s = 0.f;
#pragma unroll
        for (int i = 0; i < EDGE_WARPS_PER_BLK; i++) s += wsum[i];
        g_partials[blockIdx.x] = s;
        __threadfence();
        int done = atomicAdd(&g_edge_count, 1);
        is_last = (done == EDGE_BLOCKS - 1);
    }
    __syncthreads();

    // last block: deterministic fixed-order reduction
    if (is_last) {
        __shared__ float sh[256];
        __threadfence();
        int t = threadIdx.x;
        float v = 0.f;
#pragma unroll
        for (int i = 0; i < EDGE_BLOCKS / 256; i++)
            v += g_partials[t + i * 256];
        sh[t] = v;
        __syncthreads();
#pragma unroll
        for (int stride = 128; stride; stride >>= 1) {
            if (t < stride) sh[t] += sh[t + stride];
            __syncthreads();
        }
        if (t == 0) out[0] = sh[0];
    }
}

// ---------------------------------------------------------------------------
extern "C" void kernel_launch(void* const* d_in, const int* in_sizes, int n_in,
                              void* d_out, int out_size) {
    const int*   edges     = (const int*)  d_in[0];
    const int*   labels    = (const int*)  d_in[1];
    const int*   neighbors = (const int*)  d_in[2];
    const float* emb       = (const float*)d_in[3];
    const float* fc_w      = (const float*)d_in[4];
    const float* fc_b      = (const float*)d_in[5];
    const float* layer_w   = (const float*)d_in[6];
    const float* layer_b   = (const float*)d_in[7];
    float* out = (float*)d_out;

    proj_cw_kernel<<<PROJ_BLOCKS, 256>>>(emb, fc_w, layer_w);
    edge_kernel<<<EDGE_BLOCKS, 256>>>(emb, edges, labels, neighbors,
                                      fc_b, layer_b, out);
}